// round 12
// baseline (speedup 1.0000x reference)
#include <cuda_runtime.h>
#include <cuda_bf16.h>
#include <math.h>
#include <stdint.h>

#define Bq 64
#define Hd 1024
#define Vv 32000
#define NSTEP 50
#define NLBLK 250      // 32000 / 128 vocab tiles

typedef unsigned long long ull;

// ---------------- persistent device state (no allocation allowed) ----------
__device__ __align__(16) float g_hT[Hd * Bq];          // hidden, transposed [k][b] fp32
__device__ __align__(16) float g_c[Bq * Hd];           // cell [b][k]
__device__ __align__(16) float g_gpart[2 * Bq * 4096]; // gate partial sums
__device__ __align__(16) __nv_bfloat16 g_wt_hi[(size_t)Vv * Hd]; // W^T hi [v][k]
__device__ __align__(16) __nv_bfloat16 g_wt_lo[(size_t)Vv * Hd]; // W^T lo [v][k]
__device__ __align__(16) __nv_bfloat16 g_hb_hi[Bq * Hd];         // h hi [b][k]
__device__ __align__(16) __nv_bfloat16 g_hb_lo[Bq * Hd];         // h lo [b][k]
__device__ float g_pval[NLBLK * Bq];
__device__ int   g_pidx[NLBLK * Bq];
__device__ int   g_tok[Bq];
__device__ int   g_active;

// ---------------- packed f32x2 helpers (Blackwell FFMA2) -------------------
__device__ __forceinline__ ull pack2(float lo, float hi) {
    ull r; asm("mov.b64 %0, {%1,%2};" : "=l"(r) : "f"(lo), "f"(hi)); return r;
}
__device__ __forceinline__ float2 unpack2(ull v) {
    float2 r; asm("mov.b64 {%0,%1}, %2;" : "=f"(r.x), "=f"(r.y) : "l"(v)); return r;
}
__device__ __forceinline__ void fma2(ull &d, ull a, ull b) {
    asm("fma.rn.f32x2 %0, %1, %2, %0;" : "+l"(d) : "l"(a), "l"(b));
}

__device__ __forceinline__ uint32_t smem_u32(const void* p) {
    uint32_t a;
    asm("{ .reg .u64 t; cvta.to.shared.u64 t, %1; cvt.u32.u64 %0, t; }" : "=r"(a) : "l"(p));
    return a;
}

// bf16 mma.sync (baseline PTX, legal at compute_103 — NOT tcgen05)
__device__ __forceinline__ void mma_bf16(float* d, uint32_t a0, uint32_t a1,
                                         uint32_t a2, uint32_t a3,
                                         uint32_t b0, uint32_t b1) {
    asm volatile(
        "mma.sync.aligned.m16n8k16.row.col.f32.bf16.bf16.f32 "
        "{%0,%1,%2,%3}, {%4,%5,%6,%7}, {%8,%9}, {%0,%1,%2,%3};"
        : "+f"(d[0]), "+f"(d[1]), "+f"(d[2]), "+f"(d[3])
        : "r"(a0), "r"(a1), "r"(a2), "r"(a3), "r"(b0), "r"(b1));
}

#define CP_ASYNC16(sa, g) \
    asm volatile("cp.async.cg.shared.global [%0], [%1], 16;" :: "r"(sa), "l"(g))
#define CP_COMMIT() asm volatile("cp.async.commit_group;" ::: "memory")
#define CP_WAIT1()  asm volatile("cp.async.wait_group 1;" ::: "memory")
#define CP_WAIT0()  asm volatile("cp.async.wait_group 0;" ::: "memory")

// ---------------- init ------------------------------------------------------
__global__ void k_init(const float* __restrict__ h_in, const float* __restrict__ c_in) {
    int b = blockIdx.x;
    for (int k = threadIdx.x; k < Hd; k += blockDim.x) {
        g_hT[k * Bq + b] = h_in[b * Hd + k];
        g_c[b * Hd + k]  = c_in[b * Hd + k];
    }
    if (b == 0) {
        if (threadIdx.x < Bq) g_tok[threadIdx.x] = 1;  // SOS
        if (threadIdx.x == 0) g_active = 1;
    }
}

// ---------------- one-time (per replay) W^T bf16 hi/lo split ----------------
__global__ void k_wsplit(const float* __restrict__ out_w) {
    __shared__ float t[32][33];
    int v0 = blockIdx.x * 32, k0 = blockIdx.y * 32;
    int tx = threadIdx.x, ty = threadIdx.y;
#pragma unroll
    for (int i = 0; i < 32; i += 8)
        t[ty + i][tx] = out_w[(size_t)(k0 + ty + i) * Vv + v0 + tx];  // t[k][v]
    __syncthreads();
#pragma unroll
    for (int i = 0; i < 32; i += 8) {
        int v = ty + i;
        float val = t[tx][v];
        __nv_bfloat16 hi = __float2bfloat16(val);
        __nv_bfloat16 lo = __float2bfloat16(val - __bfloat162float(hi));
        g_wt_hi[(size_t)(v0 + v) * Hd + k0 + tx] = hi;
        g_wt_lo[(size_t)(v0 + v) * Hd + k0 + tx] = lo;
    }
}

// ---------------- gates GEMM (exact fp32 FFMA2) -----------------------------
__global__ __launch_bounds__(256) void k_gates(const float* __restrict__ emb,
                                               const float* __restrict__ w_ih,
                                               const float* __restrict__ w_hh) {
    if (*(volatile int*)&g_active == 0) return;
    __shared__ __align__(16) float s_x[64 * 64];
    __shared__ __align__(16) float s_h[64 * 64];
    __shared__ int s_tok[Bq];

    int tid = threadIdx.x;
    if (tid < Bq) s_tok[tid] = g_tok[tid];
    __syncthreads();

    int tx = tid & 31, ty = tid >> 5;
    int n = blockIdx.x * 32 + tx;
    int g = n >> 10, kcol = n & 1023;
    const float* wiP = w_ih + (size_t)g * Hd * Hd + kcol;
    const float* whP = w_hh + (size_t)g * Hd * Hd + kcol;
    int kbase = blockIdx.y * 512;

    ull acc[4] = {0ull, 0ull, 0ull, 0ull};

    for (int h0 = 0; h0 < 512; h0 += 64) {
        {
            int b = tid >> 2;
            const float* erow = emb + (size_t)s_tok[b] * Hd + kbase + h0;
#pragma unroll
            for (int j = 0; j < 4; j++) {
                int kk = ((tid & 3) + j * 4) * 4;
                float4 v = *(const float4*)(erow + kk);
                s_x[(kk + 0) * 64 + b] = v.x;
                s_x[(kk + 1) * 64 + b] = v.y;
                s_x[(kk + 2) * 64 + b] = v.z;
                s_x[(kk + 3) * 64 + b] = v.w;
            }
#pragma unroll
            for (int i = 0; i < 4; i++)
                *(float4*)(s_h + (tid + i * 256) * 4) =
                    *(const float4*)(g_hT + (kbase + h0) * Bq + (tid + i * 256) * 4);
        }
        __syncthreads();
#pragma unroll 8
        for (int k = 0; k < 64; k++) {
            size_t off = (size_t)(kbase + h0 + k) * Hd;
            float wi = wiP[off];
            float wh = whP[off];
            ull wi2 = pack2(wi, wi), wh2 = pack2(wh, wh);
            ulonglong2 Xa = *(const ulonglong2*)(s_x + k * 64 + ty * 8);
            ulonglong2 Xb = *(const ulonglong2*)(s_x + k * 64 + ty * 8 + 4);
            ulonglong2 Ha = *(const ulonglong2*)(s_h + k * 64 + ty * 8);
            ulonglong2 Hb = *(const ulonglong2*)(s_h + k * 64 + ty * 8 + 4);
            fma2(acc[0], Xa.x, wi2); fma2(acc[1], Xa.y, wi2);
            fma2(acc[2], Xb.x, wi2); fma2(acc[3], Xb.y, wi2);
            fma2(acc[0], Ha.x, wh2); fma2(acc[1], Ha.y, wh2);
            fma2(acc[2], Hb.x, wh2); fma2(acc[3], Hb.y, wh2);
        }
        __syncthreads();
    }

    float* dst = g_gpart + (size_t)blockIdx.y * Bq * 4096 + n;
    int r = ty * 8;
#pragma unroll
    for (int j = 0; j < 4; j++) {
        float2 p = unpack2(acc[j]);
        dst[(size_t)(r + 2 * j) * 4096]     = p.x;
        dst[(size_t)(r + 2 * j + 1) * 4096] = p.y;
    }
}

// ---------------- LSTM elementwise: commits h/c in place, + bf16 split ------
__global__ void k_lstm(const float* __restrict__ b_ih, const float* __restrict__ b_hh) {
    if (*(volatile int*)&g_active == 0) return;
    int b = blockIdx.x;
    const float* p0 = g_gpart + (size_t)b * 4096;
    const float* p1 = g_gpart + (size_t)Bq * 4096 + (size_t)b * 4096;
    for (int k = threadIdx.x; k < Hd; k += blockDim.x) {
        float gi = p0[k]        + p1[k]        + b_ih[k]        + b_hh[k];
        float gf = p0[1024 + k] + p1[1024 + k] + b_ih[1024 + k] + b_hh[1024 + k];
        float gc = p0[2048 + k] + p1[2048 + k] + b_ih[2048 + k] + b_hh[2048 + k];
        float go = p0[3072 + k] + p1[3072 + k] + b_ih[3072 + k] + b_hh[3072 + k];
        float ig = 1.f / (1.f + expf(-gi));
        float fg = 1.f / (1.f + expf(-gf));
        float cg = tanhf(gc);
        float og = 1.f / (1.f + expf(-go));
        float cn = fg * g_c[b * Hd + k] + ig * cg;
        float hn = og * tanhf(cn);
        g_c[b * Hd + k]  = cn;
        g_hT[k * Bq + b] = hn;
        __nv_bfloat16 hi = __float2bfloat16(hn);
        g_hb_hi[b * Hd + k] = hi;
        g_hb_lo[b * Hd + k] = __float2bfloat16(hn - __bfloat162float(hi));
    }
}

// ---------------- logits via mma.sync bf16 3-term split + fused argmax ------
// 250 blocks x 256 threads (8 warps, 4 m-warps x 2 n-warps, 32x32 warp tiles).
// Per block: M=128 vocab x N=64 batch x K=1024. KC=64 chunks, cp.async 2-stage.
// AROW must be a multiple of 16 for cp.async 16B smem alignment; 144 = 36 words
// => row-to-row bank shift of 4, fragment loads (4r+tg) hit all 32 banks.
#define KC 64
#define NCH 16
#define AROW 144
#define SM_A_HI 0
#define SM_A_LO 18432            // 128*144
#define SM_B_HI 36864
#define SM_B_LO 46080            // + 64*144
#define STAGE   55296
#define SMEM_SZ (2 * STAGE)      // 110592

__device__ __forceinline__ void stage_chunk(uint32_t sbs, int c, int v0, int tid) {
#pragma unroll
    for (int j = 0; j < 12; j++) {
        int idx = tid + j * 256;
        const __nv_bfloat16* g;
        uint32_t sa;
        if (idx < 2048) {
            int var = idx >> 10;
            int rem = idx & 1023;
            int row = rem >> 3, ch = rem & 7;
            const __nv_bfloat16* base = var ? g_wt_lo : g_wt_hi;
            g = base + (size_t)(v0 + row) * Hd + c * KC + ch * 8;
            sa = sbs + (var ? SM_A_LO : SM_A_HI) + row * AROW + ch * 16;
        } else {
            int rem = idx - 2048;
            int var = rem >> 9;
            int r2 = rem & 511;
            int row = r2 >> 3, ch = r2 & 7;
            const __nv_bfloat16* base = var ? g_hb_lo : g_hb_hi;
            g = base + (size_t)row * Hd + c * KC + ch * 8;
            sa = sbs + (var ? SM_B_LO : SM_B_HI) + row * AROW + ch * 16;
        }
        CP_ASYNC16(sa, g);
    }
}

__global__ __launch_bounds__(256, 2) void k_logits_mma(const float* __restrict__ out_b,
                                                       const float* __restrict__ std_t) {
    if (*(volatile int*)&g_active == 0) return;
    extern __shared__ __align__(16) char smem[];
    uint32_t sb = smem_u32(smem);
    int tid = threadIdx.x;
    int wid = tid >> 5, lid = tid & 31;
    int wm = wid & 3, wn = wid >> 2;
    int r = lid >> 2, tg = lid & 3;
    int v0 = blockIdx.x * 128;

    float acc[2][4][4];
#pragma unroll
    for (int ti = 0; ti < 2; ti++)
#pragma unroll
        for (int tj = 0; tj < 4; tj++)
#pragma unroll
            for (int q = 0; q < 4; q++) acc[ti][tj][q] = 0.f;

    stage_chunk(sb, 0, v0, tid);
    CP_COMMIT();

    for (int c = 0; c < NCH; c++) {
        if (c + 1 < NCH) {
            stage_chunk(sb + (uint32_t)((c + 1) & 1) * STAGE, c + 1, v0, tid);
            CP_COMMIT();
            CP_WAIT1();
        } else {
            CP_WAIT0();
        }
        __syncthreads();

        const char* base = smem + (size_t)(c & 1) * STAGE;
        const char* pAh = base + SM_A_HI;
        const char* pAl = base + SM_A_LO;
        const char* pBh = base + SM_B_HI;
        const char* pBl = base + SM_B_LO;

#pragma unroll
        for (int ks = 0; ks < KC / 16; ks++) {
            int kb0 = ks * 32 + tg * 4;       // byte offset of k-cols tg*2,tg*2+1
            uint32_t Ah[2][4], Al[2][4], Bh[4][2], Bl[4][2];
#pragma unroll
            for (int ti = 0; ti < 2; ti++) {
                int m0 = wm * 32 + ti * 16 + r;
                Ah[ti][0] = *(const uint32_t*)(pAh + m0 * AROW + kb0);
                Ah[ti][1] = *(const uint32_t*)(pAh + (m0 + 8) * AROW + kb0);
                Ah[ti][2] = *(const uint32_t*)(pAh + m0 * AROW + kb0 + 16);
                Ah[ti][3] = *(const uint32_t*)(pAh + (m0 + 8) * AROW + kb0 + 16);
                Al[ti][0] = *(const uint32_t*)(pAl + m0 * AROW + kb0);
                Al[ti][1] = *(const uint32_t*)(pAl + (m0 + 8) * AROW + kb0);
                Al[ti][2] = *(const uint32_t*)(pAl + m0 * AROW + kb0 + 16);
                Al[ti][3] = *(const uint32_t*)(pAl + (m0 + 8) * AROW + kb0 + 16);
            }
#pragma unroll
            for (int tj = 0; tj < 4; tj++) {
                int n0 = wn * 32 + tj * 8 + r;
                Bh[tj][0] = *(const uint32_t*)(pBh + n0 * AROW + kb0);
                Bh[tj][1] = *(const uint32_t*)(pBh + n0 * AROW + kb0 + 16);
                Bl[tj][0] = *(const uint32_t*)(pBl + n0 * AROW + kb0);
                Bl[tj][1] = *(const uint32_t*)(pBl + n0 * AROW + kb0 + 16);
            }
#pragma unroll
            for (int ti = 0; ti < 2; ti++)
#pragma unroll
                for (int tj = 0; tj < 4; tj++) {
                    mma_bf16(acc[ti][tj], Ah[ti][0], Ah[ti][1], Ah[ti][2], Ah[ti][3],
                             Bh[tj][0], Bh[tj][1]);
                    mma_bf16(acc[ti][tj], Ah[ti][0], Ah[ti][1], Ah[ti][2], Ah[ti][3],
                             Bl[tj][0], Bl[tj][1]);
                    mma_bf16(acc[ti][tj], Al[ti][0], Al[ti][1], Al[ti][2], Al[ti][3],
                             Bh[tj][0], Bh[tj][1]);
                }
        }
        __syncthreads();
    }

    // ---- epilogue: stage std/bias coalesced, add, warp-level argmax ----
    float* s_std  = (float*)smem;                 // [64][132] fp32
    float* s_bias = (float*)(smem + 33792);       // [128]
    float* s_rv   = (float*)(smem + 34816);       // [64 cols][4 wm]
    int*   s_ri   = (int*)(smem + 35840);
#pragma unroll
    for (int j = 0; j < 8; j++) {
        int idx = tid + j * 256;                  // 2048 float4 = 64 x 128 floats
        int row = idx >> 5, c4 = idx & 31;
        float4 v = *(const float4*)(std_t + (size_t)row * Vv + v0 + c4 * 4);
        *(float4*)(s_std + row * 132 + c4 * 4) = v;
    }
    if (tid < 32) ((float4*)s_bias)[tid] = ((const float4*)(out_b + v0))[tid];
    __syncthreads();

#pragma unroll
    for (int tj = 0; tj < 4; tj++) {
#pragma unroll
        for (int p = 0; p < 2; p++) {
            int n = wn * 32 + tj * 8 + tg * 2 + p;
            float best = -1e30f;
            int bi = 0x7fffffff;
#pragma unroll
            for (int ti = 0; ti < 2; ti++)
#pragma unroll
                for (int hh = 0; hh < 2; hh++) {
                    int row = wm * 32 + ti * 16 + r + hh * 8;
                    float val = acc[ti][tj][hh * 2 + p] + s_bias[row] + s_std[n * 132 + row];
                    int idx = v0 + row;
                    if (val > best || (val == best && idx < bi)) { best = val; bi = idx; }
                }
#pragma unroll
            for (int o = 16; o >= 4; o >>= 1) {
                float ov = __shfl_down_sync(0xffffffffu, best, o);
                int oi   = __shfl_down_sync(0xffffffffu, bi, o);
                if (ov > best || (ov == best && oi < bi)) { best = ov; bi = oi; }
            }
            if (lid < 4) {
                s_rv[n * 4 + wm] = best;
                s_ri[n * 4 + wm] = bi;
            }
        }
    }
    __syncthreads();
    if (tid < 64) {
        float best = -1e30f;
        int bi = 0x7fffffff;
#pragma unroll
        for (int j = 0; j < 4; j++) {
            float vv = s_rv[tid * 4 + j];
            int ii = s_ri[tid * 4 + j];
            if (vv > best || (vv == best && ii < bi)) { best = vv; bi = ii; }
        }
        g_pval[blockIdx.x * Bq + tid] = best;
        g_pidx[blockIdx.x * Bq + tid] = bi;
    }
}

// ---------------- finalize argmax, token/active bookkeeping ----------------
__global__ void k_decide(float* __restrict__ out_tok, int write_tok) {
    __shared__ int s_max[2];
    int b = threadIdx.x;  // 64 threads
    int active = *(volatile int*)&g_active;
    float best = -1e30f;
    int bi = 0;
    if (active) {
#pragma unroll 10
        for (int blk = 0; blk < NLBLK; blk++) {
            float v = g_pval[blk * Bq + b];
            int   i = g_pidx[blk * Bq + b];
            if (v > best || (v == best && i < bi)) { best = v; bi = i; }
        }
        if (write_tok) out_tok[b] = (float)bi;
        g_tok[b] = bi;
    } else {
        if (write_tok) out_tok[b] = 0.0f;
    }
    int m = bi;
#pragma unroll
    for (int o = 16; o > 0; o >>= 1)
        m = max(m, __shfl_down_sync(0xffffffffu, m, o));
    if ((b & 31) == 0) s_max[b >> 5] = m;
    __syncthreads();
    if (b == 0 && active)
        g_active = (max(s_max[0], s_max[1]) > 0) ? 1 : 0;
}

// ---------------- write final hidden state ---------------------------------
__global__ void k_final(float* __restrict__ out_h) {
    int b = blockIdx.x;
    for (int k = threadIdx.x; k < Hd; k += blockDim.x)
        out_h[b * Hd + k] = g_hT[k * Bq + b];
}

// ---------------- launcher -------------------------------------------------
extern "C" void kernel_launch(void* const* d_in, const int* in_sizes, int n_in,
                              void* d_out, int out_size) {
    const float* std_in = (const float*)d_in[1];
    const float* h_in   = (const float*)d_in[2];
    const float* c_in   = (const float*)d_in[3];
    const float* emb    = (const float*)d_in[4];
    const float* w_ih   = (const float*)d_in[5];
    const float* w_hh   = (const float*)d_in[6];
    const float* b_ih   = (const float*)d_in[7];
    const float* b_hh   = (const float*)d_in[8];
    const float* out_w  = (const float*)d_in[9];
    const float* out_b  = (const float*)d_in[10];
    float* out = (float*)d_out;

    int write_tok = (out_size >= NSTEP * Bq) ? 1 : 0;
    int write_h   = (out_size == Hd * Bq || out_size >= NSTEP * Bq + Hd * Bq) ? 1 : 0;
    int h_off     = (out_size >= NSTEP * Bq + Hd * Bq) ? NSTEP * Bq : 0;

    cudaFuncSetAttribute(k_logits_mma, cudaFuncAttributeMaxDynamicSharedMemorySize, SMEM_SZ);

    k_init<<<Bq, 256>>>(h_in, c_in);
    k_wsplit<<<dim3(1000, 32), dim3(32, 8)>>>(out_w);
    for (int t = 0; t < NSTEP; t++) {
        k_gates<<<dim3(128, 2), 256>>>(emb, w_ih, w_hh);
        k_lstm<<<Bq, 256>>>(b_ih, b_hh);
        k_logits_mma<<<NLBLK, 256, SMEM_SZ>>>(out_b, std_in + (size_t)t * Bq * Vv);
        k_decide<<<1, Bq>>>(out + (size_t)t * Bq, write_tok);
    }
    if (write_h) k_final<<<Bq, 256>>>(out + h_off);
}

// round 15
// speedup vs baseline: 1.3519x; 1.3519x over previous
#include <cuda_runtime.h>
#include <cuda_bf16.h>
#include <math.h>
#include <stdint.h>

#define Bq 64
#define Hd 1024
#define Vv 32000
#define NSTEP 50
#define NLBLK 250      // 32000 / 128 vocab tiles

typedef unsigned long long ull;

// ---------------- persistent device state (no allocation allowed) ----------
__device__ __align__(16) float g_hT[Hd * Bq];          // hidden, transposed [k][b] fp32
__device__ __align__(16) float g_c[Bq * Hd];           // cell [b][k]
__device__ __align__(16) float g_gpart[2 * Bq * 4096]; // gate partial sums
__device__ __align__(16) __nv_bfloat16 g_wt_hi[(size_t)Vv * Hd]; // W^T hi [v][k]
__device__ __align__(16) __nv_bfloat16 g_wt_lo[(size_t)Vv * Hd]; // W^T lo [v][k]
__device__ __align__(16) __nv_bfloat16 g_hb_hi[Bq * Hd];         // h hi [b][k]
__device__ __align__(16) __nv_bfloat16 g_hb_lo[Bq * Hd];         // h lo [b][k]
__device__ float g_pval[NLBLK * Bq];
__device__ int   g_pidx[NLBLK * Bq];
__device__ int   g_tok[Bq];
__device__ int   g_active;

// ---------------- packed f32x2 helpers (Blackwell FFMA2) -------------------
__device__ __forceinline__ ull pack2(float lo, float hi) {
    ull r; asm("mov.b64 %0, {%1,%2};" : "=l"(r) : "f"(lo), "f"(hi)); return r;
}
__device__ __forceinline__ float2 unpack2(ull v) {
    float2 r; asm("mov.b64 {%0,%1}, %2;" : "=f"(r.x), "=f"(r.y) : "l"(v)); return r;
}
__device__ __forceinline__ void fma2(ull &d, ull a, ull b) {
    asm("fma.rn.f32x2 %0, %1, %2, %0;" : "+l"(d) : "l"(a), "l"(b));
}

__device__ __forceinline__ uint32_t smem_u32(const void* p) {
    uint32_t a;
    asm("{ .reg .u64 t; cvta.to.shared.u64 t, %1; cvt.u32.u64 %0, t; }" : "=r"(a) : "l"(p));
    return a;
}

// bf16 mma.sync (baseline PTX, legal at compute_103 — NOT tcgen05)
__device__ __forceinline__ void mma_bf16(float* d, uint32_t a0, uint32_t a1,
                                         uint32_t a2, uint32_t a3,
                                         uint32_t b0, uint32_t b1) {
    asm volatile(
        "mma.sync.aligned.m16n8k16.row.col.f32.bf16.bf16.f32 "
        "{%0,%1,%2,%3}, {%4,%5,%6,%7}, {%8,%9}, {%0,%1,%2,%3};"
        : "+f"(d[0]), "+f"(d[1]), "+f"(d[2]), "+f"(d[3])
        : "r"(a0), "r"(a1), "r"(a2), "r"(a3), "r"(b0), "r"(b1));
}

#define CP_ASYNC16(sa, g) \
    asm volatile("cp.async.cg.shared.global [%0], [%1], 16;" :: "r"(sa), "l"(g))
#define CP_COMMIT() asm volatile("cp.async.commit_group;" ::: "memory")
#define CP_WAIT1()  asm volatile("cp.async.wait_group 1;" ::: "memory")
#define CP_WAIT0()  asm volatile("cp.async.wait_group 0;" ::: "memory")

// ---------------- init ------------------------------------------------------
__global__ void k_init(const float* __restrict__ h_in, const float* __restrict__ c_in) {
    int b = blockIdx.x;
    for (int k = threadIdx.x; k < Hd; k += blockDim.x) {
        g_hT[k * Bq + b] = h_in[b * Hd + k];
        g_c[b * Hd + k]  = c_in[b * Hd + k];
    }
    if (b == 0) {
        if (threadIdx.x < Bq) g_tok[threadIdx.x] = 1;  // SOS
        if (threadIdx.x == 0) g_active = 1;
    }
}

// ---------------- one-time (per replay) W^T bf16 hi/lo split ----------------
__global__ void k_wsplit(const float* __restrict__ out_w) {
    __shared__ float t[32][33];
    int v0 = blockIdx.x * 32, k0 = blockIdx.y * 32;
    int tx = threadIdx.x, ty = threadIdx.y;
#pragma unroll
    for (int i = 0; i < 32; i += 8)
        t[ty + i][tx] = out_w[(size_t)(k0 + ty + i) * Vv + v0 + tx];  // t[k][v]
    __syncthreads();
#pragma unroll
    for (int i = 0; i < 32; i += 8) {
        int v = ty + i;
        float val = t[tx][v];
        __nv_bfloat16 hi = __float2bfloat16(val);
        __nv_bfloat16 lo = __float2bfloat16(val - __bfloat162float(hi));
        g_wt_hi[(size_t)(v0 + v) * Hd + k0 + tx] = hi;
        g_wt_lo[(size_t)(v0 + v) * Hd + k0 + tx] = lo;
    }
}

// ---------------- gates GEMM (exact fp32 FFMA2) -----------------------------
__global__ __launch_bounds__(256) void k_gates(const float* __restrict__ emb,
                                               const float* __restrict__ w_ih,
                                               const float* __restrict__ w_hh) {
    if (*(volatile int*)&g_active == 0) return;
    __shared__ __align__(16) float s_x[64 * 64];
    __shared__ __align__(16) float s_h[64 * 64];
    __shared__ int s_tok[Bq];

    int tid = threadIdx.x;
    if (tid < Bq) s_tok[tid] = g_tok[tid];
    __syncthreads();

    int tx = tid & 31, ty = tid >> 5;
    int n = blockIdx.x * 32 + tx;
    int g = n >> 10, kcol = n & 1023;
    const float* wiP = w_ih + (size_t)g * Hd * Hd + kcol;
    const float* whP = w_hh + (size_t)g * Hd * Hd + kcol;
    int kbase = blockIdx.y * 512;

    ull acc[4] = {0ull, 0ull, 0ull, 0ull};

    for (int h0 = 0; h0 < 512; h0 += 64) {
        {
            int b = tid >> 2;
            const float* erow = emb + (size_t)s_tok[b] * Hd + kbase + h0;
#pragma unroll
            for (int j = 0; j < 4; j++) {
                int kk = ((tid & 3) + j * 4) * 4;
                float4 v = *(const float4*)(erow + kk);
                s_x[(kk + 0) * 64 + b] = v.x;
                s_x[(kk + 1) * 64 + b] = v.y;
                s_x[(kk + 2) * 64 + b] = v.z;
                s_x[(kk + 3) * 64 + b] = v.w;
            }
#pragma unroll
            for (int i = 0; i < 4; i++)
                *(float4*)(s_h + (tid + i * 256) * 4) =
                    *(const float4*)(g_hT + (kbase + h0) * Bq + (tid + i * 256) * 4);
        }
        __syncthreads();
#pragma unroll 8
        for (int k = 0; k < 64; k++) {
            size_t off = (size_t)(kbase + h0 + k) * Hd;
            float wi = wiP[off];
            float wh = whP[off];
            ull wi2 = pack2(wi, wi), wh2 = pack2(wh, wh);
            ulonglong2 Xa = *(const ulonglong2*)(s_x + k * 64 + ty * 8);
            ulonglong2 Xb = *(const ulonglong2*)(s_x + k * 64 + ty * 8 + 4);
            ulonglong2 Ha = *(const ulonglong2*)(s_h + k * 64 + ty * 8);
            ulonglong2 Hb = *(const ulonglong2*)(s_h + k * 64 + ty * 8 + 4);
            fma2(acc[0], Xa.x, wi2); fma2(acc[1], Xa.y, wi2);
            fma2(acc[2], Xb.x, wi2); fma2(acc[3], Xb.y, wi2);
            fma2(acc[0], Ha.x, wh2); fma2(acc[1], Ha.y, wh2);
            fma2(acc[2], Hb.x, wh2); fma2(acc[3], Hb.y, wh2);
        }
        __syncthreads();
    }

    float* dst = g_gpart + (size_t)blockIdx.y * Bq * 4096 + n;
    int r = ty * 8;
#pragma unroll
    for (int j = 0; j < 4; j++) {
        float2 p = unpack2(acc[j]);
        dst[(size_t)(r + 2 * j) * 4096]     = p.x;
        dst[(size_t)(r + 2 * j + 1) * 4096] = p.y;
    }
}

// ---------------- LSTM elementwise: commits h/c in place, + bf16 split ------
__global__ void k_lstm(const float* __restrict__ b_ih, const float* __restrict__ b_hh) {
    if (*(volatile int*)&g_active == 0) return;
    int b = blockIdx.x;
    const float* p0 = g_gpart + (size_t)b * 4096;
    const float* p1 = g_gpart + (size_t)Bq * 4096 + (size_t)b * 4096;
    for (int k = threadIdx.x; k < Hd; k += blockDim.x) {
        float gi = p0[k]        + p1[k]        + b_ih[k]        + b_hh[k];
        float gf = p0[1024 + k] + p1[1024 + k] + b_ih[1024 + k] + b_hh[1024 + k];
        float gc = p0[2048 + k] + p1[2048 + k] + b_ih[2048 + k] + b_hh[2048 + k];
        float go = p0[3072 + k] + p1[3072 + k] + b_ih[3072 + k] + b_hh[3072 + k];
        float ig = 1.f / (1.f + expf(-gi));
        float fg = 1.f / (1.f + expf(-gf));
        float cg = tanhf(gc);
        float og = 1.f / (1.f + expf(-go));
        float cn = fg * g_c[b * Hd + k] + ig * cg;
        float hn = og * tanhf(cn);
        g_c[b * Hd + k]  = cn;
        g_hT[k * Bq + b] = hn;
        __nv_bfloat16 hi = __float2bfloat16(hn);
        g_hb_hi[b * Hd + k] = hi;
        g_hb_lo[b * Hd + k] = __float2bfloat16(hn - __bfloat162float(hi));
    }
}

// ---------------- logits via mma.sync bf16 3-term split + fused argmax ------
// 250 blocks x 256 threads (8 warps, 4 m-warps x 2 n-warps, 32x32 warp tiles).
// Per block: M=128 vocab x N=64 batch x K=1024. KC=64 chunks, cp.async 2-stage.
// AROW must be a multiple of 16 for cp.async 16B smem alignment; 144 = 36 words
// => row-to-row bank shift of 4, fragment loads (4r+tg) hit all 32 banks.
#define KC 64
#define NCH 16
#define AROW 144
#define SM_A_HI 0
#define SM_A_LO 18432            // 128*144
#define SM_B_HI 36864
#define SM_B_LO 46080            // + 64*144
#define STAGE   55296
#define SMEM_SZ (2 * STAGE)      // 110592

__device__ __forceinline__ void stage_chunk(uint32_t sbs, int c, int v0, int tid) {
#pragma unroll
    for (int j = 0; j < 12; j++) {
        int idx = tid + j * 256;
        const __nv_bfloat16* g;
        uint32_t sa;
        if (idx < 2048) {
            int var = idx >> 10;
            int rem = idx & 1023;
            int row = rem >> 3, ch = rem & 7;
            const __nv_bfloat16* base = var ? g_wt_lo : g_wt_hi;
            g = base + (size_t)(v0 + row) * Hd + c * KC + ch * 8;
            sa = sbs + (var ? SM_A_LO : SM_A_HI) + row * AROW + ch * 16;
        } else {
            int rem = idx - 2048;
            int var = rem >> 9;
            int r2 = rem & 511;
            int row = r2 >> 3, ch = r2 & 7;
            const __nv_bfloat16* base = var ? g_hb_lo : g_hb_hi;
            g = base + (size_t)row * Hd + c * KC + ch * 8;
            sa = sbs + (var ? SM_B_LO : SM_B_HI) + row * AROW + ch * 16;
        }
        CP_ASYNC16(sa, g);
    }
}

__global__ __launch_bounds__(256, 2) void k_logits_mma(const float* __restrict__ out_b,
                                                       const float* __restrict__ std_t) {
    if (*(volatile int*)&g_active == 0) return;
    extern __shared__ __align__(16) char smem[];
    uint32_t sb = smem_u32(smem);
    int tid = threadIdx.x;
    int wid = tid >> 5, lid = tid & 31;
    int wm = wid & 3, wn = wid >> 2;
    int r = lid >> 2, tg = lid & 3;
    int v0 = blockIdx.x * 128;

    float acc[2][4][4];
#pragma unroll
    for (int ti = 0; ti < 2; ti++)
#pragma unroll
        for (int tj = 0; tj < 4; tj++)
#pragma unroll
            for (int q = 0; q < 4; q++) acc[ti][tj][q] = 0.f;

    stage_chunk(sb, 0, v0, tid);
    CP_COMMIT();

    for (int c = 0; c < NCH; c++) {
        if (c + 1 < NCH) {
            stage_chunk(sb + (uint32_t)((c + 1) & 1) * STAGE, c + 1, v0, tid);
            CP_COMMIT();
            CP_WAIT1();
        } else {
            CP_WAIT0();
        }
        __syncthreads();

        const char* base = smem + (size_t)(c & 1) * STAGE;
        const char* pAh = base + SM_A_HI;
        const char* pAl = base + SM_A_LO;
        const char* pBh = base + SM_B_HI;
        const char* pBl = base + SM_B_LO;

#pragma unroll
        for (int ks = 0; ks < KC / 16; ks++) {
            int kb0 = ks * 32 + tg * 4;       // byte offset of k-cols tg*2,tg*2+1
            uint32_t Ah[2][4], Al[2][4], Bh[4][2], Bl[4][2];
#pragma unroll
            for (int ti = 0; ti < 2; ti++) {
                int m0 = wm * 32 + ti * 16 + r;
                Ah[ti][0] = *(const uint32_t*)(pAh + m0 * AROW + kb0);
                Ah[ti][1] = *(const uint32_t*)(pAh + (m0 + 8) * AROW + kb0);
                Ah[ti][2] = *(const uint32_t*)(pAh + m0 * AROW + kb0 + 16);
                Ah[ti][3] = *(const uint32_t*)(pAh + (m0 + 8) * AROW + kb0 + 16);
                Al[ti][0] = *(const uint32_t*)(pAl + m0 * AROW + kb0);
                Al[ti][1] = *(const uint32_t*)(pAl + (m0 + 8) * AROW + kb0);
                Al[ti][2] = *(const uint32_t*)(pAl + m0 * AROW + kb0 + 16);
                Al[ti][3] = *(const uint32_t*)(pAl + (m0 + 8) * AROW + kb0 + 16);
            }
#pragma unroll
            for (int tj = 0; tj < 4; tj++) {
                int n0 = wn * 32 + tj * 8 + r;
                Bh[tj][0] = *(const uint32_t*)(pBh + n0 * AROW + kb0);
                Bh[tj][1] = *(const uint32_t*)(pBh + n0 * AROW + kb0 + 16);
                Bl[tj][0] = *(const uint32_t*)(pBl + n0 * AROW + kb0);
                Bl[tj][1] = *(const uint32_t*)(pBl + n0 * AROW + kb0 + 16);
            }
#pragma unroll
            for (int ti = 0; ti < 2; ti++)
#pragma unroll
                for (int tj = 0; tj < 4; tj++) {
                    mma_bf16(acc[ti][tj], Ah[ti][0], Ah[ti][1], Ah[ti][2], Ah[ti][3],
                             Bh[tj][0], Bh[tj][1]);
                    mma_bf16(acc[ti][tj], Ah[ti][0], Ah[ti][1], Ah[ti][2], Ah[ti][3],
                             Bl[tj][0], Bl[tj][1]);
                    mma_bf16(acc[ti][tj], Al[ti][0], Al[ti][1], Al[ti][2], Al[ti][3],
                             Bh[tj][0], Bh[tj][1]);
                }
        }
        __syncthreads();
    }

    // ---- epilogue: stage std/bias coalesced, add, warp-level argmax ----
    float* s_std  = (float*)smem;                 // [64][132] fp32
    float* s_bias = (float*)(smem + 33792);       // [128]
    float* s_rv   = (float*)(smem + 34816);       // [64 cols][4 wm]
    int*   s_ri   = (int*)(smem + 35840);
#pragma unroll
    for (int j = 0; j < 8; j++) {
        int idx = tid + j * 256;                  // 2048 float4 = 64 x 128 floats
        int row = idx >> 5, c4 = idx & 31;
        float4 v = *(const float4*)(std_t + (size_t)row * Vv + v0 + c4 * 4);
        *(float4*)(s_std + row * 132 + c4 * 4) = v;
    }
    if (tid < 32) ((float4*)s_bias)[tid] = ((const float4*)(out_b + v0))[tid];
    __syncthreads();

#pragma unroll
    for (int tj = 0; tj < 4; tj++) {
#pragma unroll
        for (int p = 0; p < 2; p++) {
            int n = wn * 32 + tj * 8 + tg * 2 + p;
            float best = -1e30f;
            int bi = 0x7fffffff;
#pragma unroll
            for (int ti = 0; ti < 2; ti++)
#pragma unroll
                for (int hh = 0; hh < 2; hh++) {
                    int row = wm * 32 + ti * 16 + r + hh * 8;
                    float val = acc[ti][tj][hh * 2 + p] + s_bias[row] + s_std[n * 132 + row];
                    int idx = v0 + row;
                    if (val > best || (val == best && idx < bi)) { best = val; bi = idx; }
                }
#pragma unroll
            for (int o = 16; o >= 4; o >>= 1) {
                float ov = __shfl_down_sync(0xffffffffu, best, o);
                int oi   = __shfl_down_sync(0xffffffffu, bi, o);
                if (ov > best || (ov == best && oi < bi)) { best = ov; bi = oi; }
            }
            if (lid < 4) {
                s_rv[n * 4 + wm] = best;
                s_ri[n * 4 + wm] = bi;
            }
        }
    }
    __syncthreads();
    if (tid < 64) {
        float best = -1e30f;
        int bi = 0x7fffffff;
#pragma unroll
        for (int j = 0; j < 4; j++) {
            float vv = s_rv[tid * 4 + j];
            int ii = s_ri[tid * 4 + j];
            if (vv > best || (vv == best && ii < bi)) { best = vv; bi = ii; }
        }
        g_pval[blockIdx.x * Bq + tid] = best;
        g_pidx[blockIdx.x * Bq + tid] = bi;
    }
}

// ---------------- finalize argmax, token/active bookkeeping ----------------
__global__ void k_decide(float* __restrict__ out_tok, int write_tok) {
    __shared__ int s_max[2];
    int b = threadIdx.x;  // 64 threads
    int active = *(volatile int*)&g_active;
    float best = -1e30f;
    int bi = 0;
    if (active) {
#pragma unroll 10
        for (int blk = 0; blk < NLBLK; blk++) {
            float v = g_pval[blk * Bq + b];
            int   i = g_pidx[blk * Bq + b];
            if (v > best || (v == best && i < bi)) { best = v; bi = i; }
        }
        if (write_tok) out_tok[b] = (float)bi;
        g_tok[b] = bi;
    } else {
        if (write_tok) out_tok[b] = 0.0f;
    }
    int m = bi;
#pragma unroll
    for (int o = 16; o > 0; o >>= 1)
        m = max(m, __shfl_down_sync(0xffffffffu, m, o));
    if ((b & 31) == 0) s_max[b >> 5] = m;
    __syncthreads();
    if (b == 0 && active)
        g_active = (max(s_max[0], s_max[1]) > 0) ? 1 : 0;
}

// ---------------- write final hidden state ---------------------------------
__global__ void k_final(float* __restrict__ out_h) {
    int b = blockIdx.x;
    for (int k = threadIdx.x; k < Hd; k += blockDim.x)
        out_h[b * Hd + k] = g_hT[k * Bq + b];
}

// ---------------- launcher -------------------------------------------------
extern "C" void kernel_launch(void* const* d_in, const int* in_sizes, int n_in,
                              void* d_out, int out_size) {
    const float* std_in = (const float*)d_in[1];
    const float* h_in   = (const float*)d_in[2];
    const float* c_in   = (const float*)d_in[3];
    const float* emb    = (const float*)d_in[4];
    const float* w_ih   = (const float*)d_in[5];
    const float* w_hh   = (const float*)d_in[6];
    const float* b_ih   = (const float*)d_in[7];
    const float* b_hh   = (const float*)d_in[8];
    const float* out_w  = (const float*)d_in[9];
    const float* out_b  = (const float*)d_in[10];
    float* out = (float*)d_out;

    int write_tok = (out_size >= NSTEP * Bq) ? 1 : 0;
    int write_h   = (out_size == Hd * Bq || out_size >= NSTEP * Bq + Hd * Bq) ? 1 : 0;
    int h_off     = (out_size >= NSTEP * Bq + Hd * Bq) ? NSTEP * Bq : 0;

    cudaFuncSetAttribute(k_logits_mma, cudaFuncAttributeMaxDynamicSharedMemorySize, SMEM_SZ);

    k_init<<<Bq, 256>>>(h_in, c_in);
    k_wsplit<<<dim3(1000, 32), dim3(32, 8)>>>(out_w);
    for (int t = 0; t < NSTEP; t++) {
        k_gates<<<dim3(128, 2), 256>>>(emb, w_ih, w_hh);
        k_lstm<<<Bq, 256>>>(b_ih, b_hh);
        k_logits_mma<<<NLBLK, 256, SMEM_SZ>>>(out_b, std_in + (size_t)t * Bq * Vv);
        k_decide<<<1, Bq>>>(out + (size_t)t * Bq, write_tok);
    }
    if (write_h) k_final<<<Bq, 256>>>(out + h_off);
}

// round 16
// speedup vs baseline: 1.7404x; 1.2874x over previous
#include <cuda_runtime.h>
#include <cuda_bf16.h>
#include <math.h>
#include <stdint.h>

#define Bq 64
#define Hd 1024
#define Vv 32000
#define NSTEP 50
#define NLBLK 250      // 32000 / 128 vocab tiles

typedef unsigned long long ull;

// ---------------- persistent device state (no allocation allowed) ----------
__device__ __align__(16) float g_hT[Hd * Bq];          // hidden, transposed [k][b] fp32
__device__ __align__(16) float g_c[Bq * Hd];           // cell [b][k]
__device__ __align__(16) float g_gpart[2 * Bq * 4096]; // gate partial sums
__device__ __align__(16) __nv_bfloat16 g_wt_hi[(size_t)Vv * Hd]; // W^T hi [v][k]
__device__ __align__(16) __nv_bfloat16 g_wt_lo[(size_t)Vv * Hd]; // W^T lo [v][k]
__device__ __align__(16) __nv_bfloat16 g_hb_hi[Bq * Hd];         // h hi [b][k]
__device__ __align__(16) __nv_bfloat16 g_hb_lo[Bq * Hd];         // h lo [b][k]
__device__ float g_pval[NLBLK * Bq];                   // [blk][b]
__device__ int   g_pidx[NLBLK * Bq];
__device__ int   g_tok[Bq];
__device__ int   g_active;
__device__ int   g_barg;                               // gates grid-barrier ticket
__device__ int   g_ldone;                              // logits last-block ticket

// ---------------- packed f32x2 helpers (Blackwell FFMA2) -------------------
__device__ __forceinline__ ull pack2(float lo, float hi) {
    ull r; asm("mov.b64 %0, {%1,%2};" : "=l"(r) : "f"(lo), "f"(hi)); return r;
}
__device__ __forceinline__ float2 unpack2(ull v) {
    float2 r; asm("mov.b64 {%0,%1}, %2;" : "=f"(r.x), "=f"(r.y) : "l"(v)); return r;
}
__device__ __forceinline__ void fma2(ull &d, ull a, ull b) {
    asm("fma.rn.f32x2 %0, %1, %2, %0;" : "+l"(d) : "l"(a), "l"(b));
}
__device__ __forceinline__ uint32_t smem_u32(const void* p) {
    uint32_t a;
    asm("{ .reg .u64 t; cvta.to.shared.u64 t, %1; cvt.u32.u64 %0, t; }" : "=r"(a) : "l"(p));
    return a;
}

// bf16 mma.sync (baseline PTX, legal at compute_103)
__device__ __forceinline__ void mma_bf16(float* d, uint32_t a0, uint32_t a1,
                                         uint32_t a2, uint32_t a3,
                                         uint32_t b0, uint32_t b1) {
    asm volatile(
        "mma.sync.aligned.m16n8k16.row.col.f32.bf16.bf16.f32 "
        "{%0,%1,%2,%3}, {%4,%5,%6,%7}, {%8,%9}, {%0,%1,%2,%3};"
        : "+f"(d[0]), "+f"(d[1]), "+f"(d[2]), "+f"(d[3])
        : "r"(a0), "r"(a1), "r"(a2), "r"(a3), "r"(b0), "r"(b1));
}

#define CP_ASYNC16(sa, g) \
    asm volatile("cp.async.cg.shared.global [%0], [%1], 16;" :: "r"(sa), "l"(g))
#define CP_COMMIT() asm volatile("cp.async.commit_group;" ::: "memory")
#define CP_WAIT1()  asm volatile("cp.async.wait_group 1;" ::: "memory")
#define CP_WAIT0()  asm volatile("cp.async.wait_group 0;" ::: "memory")

// ---------------- init ------------------------------------------------------
__global__ void k_init(const float* __restrict__ h_in, const float* __restrict__ c_in) {
    int b = blockIdx.x;
    for (int k = threadIdx.x; k < Hd; k += blockDim.x) {
        g_hT[k * Bq + b] = h_in[b * Hd + k];
        g_c[b * Hd + k]  = c_in[b * Hd + k];
    }
    if (b == 0) {
        if (threadIdx.x < Bq) g_tok[threadIdx.x] = 1;  // SOS
        if (threadIdx.x == 0) { g_active = 1; g_barg = 0; g_ldone = 0; }
    }
}

// ---------------- one-time (per replay) W^T bf16 hi/lo split ----------------
__global__ void k_wsplit(const float* __restrict__ out_w) {
    __shared__ float t[32][33];
    int v0 = blockIdx.x * 32, k0 = blockIdx.y * 32;
    int tx = threadIdx.x, ty = threadIdx.y;
#pragma unroll
    for (int i = 0; i < 32; i += 8)
        t[ty + i][tx] = out_w[(size_t)(k0 + ty + i) * Vv + v0 + tx];  // t[k][v]
    __syncthreads();
#pragma unroll
    for (int i = 0; i < 32; i += 8) {
        int v = ty + i;
        float val = t[tx][v];
        __nv_bfloat16 hi = __float2bfloat16(val);
        __nv_bfloat16 lo = __float2bfloat16(val - __bfloat162float(hi));
        g_wt_hi[(size_t)(v0 + v) * Hd + k0 + tx] = hi;
        g_wt_lo[(size_t)(v0 + v) * Hd + k0 + tx] = lo;
    }
}

// ---------------- gates GEMM (fp32 FFMA2) + grid barrier + fused LSTM -------
// grid (128,2) = 256 blocks; __launch_bounds__(256,2) + 33KB smem => 2 CTA/SM
// => all 256 blocks co-resident (296 slots) => grid barrier is deadlock-free.
__global__ __launch_bounds__(256, 2) void k_gateslstm(
        const float* __restrict__ emb, const float* __restrict__ w_ih,
        const float* __restrict__ w_hh, const float* __restrict__ b_ih,
        const float* __restrict__ b_hh) {
    if (*(volatile int*)&g_active == 0) return;   // uniform across blocks
    __shared__ __align__(16) float s_x[64 * 64];
    __shared__ __align__(16) float s_h[64 * 64];
    __shared__ int s_tok[Bq];
    __shared__ int s_tgt;

    int tid = threadIdx.x;
    int flat = blockIdx.y * 128 + blockIdx.x;
    if (tid < Bq) s_tok[tid] = g_tok[tid];
    __syncthreads();

    int tx = tid & 31, ty = tid >> 5;
    int n = blockIdx.x * 32 + tx;
    int g = n >> 10, kcol = n & 1023;
    const float* wiP = w_ih + (size_t)g * Hd * Hd + kcol;
    const float* whP = w_hh + (size_t)g * Hd * Hd + kcol;
    int kbase = blockIdx.y * 512;

    ull acc[4] = {0ull, 0ull, 0ull, 0ull};

    for (int h0 = 0; h0 < 512; h0 += 64) {
        {
            int b = tid >> 2;
            const float* erow = emb + (size_t)s_tok[b] * Hd + kbase + h0;
#pragma unroll
            for (int j = 0; j < 4; j++) {
                int kk = ((tid & 3) + j * 4) * 4;
                float4 v = *(const float4*)(erow + kk);
                s_x[(kk + 0) * 64 + b] = v.x;
                s_x[(kk + 1) * 64 + b] = v.y;
                s_x[(kk + 2) * 64 + b] = v.z;
                s_x[(kk + 3) * 64 + b] = v.w;
            }
#pragma unroll
            for (int i = 0; i < 4; i++)
                *(float4*)(s_h + (tid + i * 256) * 4) =
                    *(const float4*)(g_hT + (kbase + h0) * Bq + (tid + i * 256) * 4);
        }
        __syncthreads();
#pragma unroll 8
        for (int k = 0; k < 64; k++) {
            size_t off = (size_t)(kbase + h0 + k) * Hd;
            float wi = wiP[off];
            float wh = whP[off];
            ull wi2 = pack2(wi, wi), wh2 = pack2(wh, wh);
            ulonglong2 Xa = *(const ulonglong2*)(s_x + k * 64 + ty * 8);
            ulonglong2 Xb = *(const ulonglong2*)(s_x + k * 64 + ty * 8 + 4);
            ulonglong2 Ha = *(const ulonglong2*)(s_h + k * 64 + ty * 8);
            ulonglong2 Hb = *(const ulonglong2*)(s_h + k * 64 + ty * 8 + 4);
            fma2(acc[0], Xa.x, wi2); fma2(acc[1], Xa.y, wi2);
            fma2(acc[2], Xb.x, wi2); fma2(acc[3], Xb.y, wi2);
            fma2(acc[0], Ha.x, wh2); fma2(acc[1], Ha.y, wh2);
            fma2(acc[2], Hb.x, wh2); fma2(acc[3], Hb.y, wh2);
        }
        __syncthreads();
    }

    {
        float* dst = g_gpart + (size_t)blockIdx.y * Bq * 4096 + n;
        int r = ty * 8;
#pragma unroll
        for (int j = 0; j < 4; j++) {
            float2 p = unpack2(acc[j]);
            dst[(size_t)(r + 2 * j) * 4096]     = p.x;
            dst[(size_t)(r + 2 * j + 1) * 4096] = p.y;
        }
    }

    // ---- grid barrier (monotonic ticket; k_init resets to 0 each replay) ----
    __syncthreads();
    __threadfence();
    if (tid == 0) {
        int t0 = atomicAdd(&g_barg, 1);
        s_tgt = (t0 / 256) * 256 + 256;
        while (*(volatile int*)&g_barg < s_tgt) __nanosleep(64);
    }
    __syncthreads();
    __threadfence();

    // ---- fused LSTM: 65536 threads, 1 element each ----
    {
        int e = flat * 256 + tid;
        int b = e >> 10, k = e & 1023;
        const float* p0 = g_gpart + (size_t)b * 4096;
        const float* p1 = g_gpart + (size_t)Bq * 4096 + (size_t)b * 4096;
        float gi = __ldcg(p0 + k)        + __ldcg(p1 + k)        + b_ih[k]        + b_hh[k];
        float gf = __ldcg(p0 + 1024 + k) + __ldcg(p1 + 1024 + k) + b_ih[1024 + k] + b_hh[1024 + k];
        float gc = __ldcg(p0 + 2048 + k) + __ldcg(p1 + 2048 + k) + b_ih[2048 + k] + b_hh[2048 + k];
        float go = __ldcg(p0 + 3072 + k) + __ldcg(p1 + 3072 + k) + b_ih[3072 + k] + b_hh[3072 + k];
        float ig = 1.f / (1.f + expf(-gi));
        float fg = 1.f / (1.f + expf(-gf));
        float cg = tanhf(gc);
        float og = 1.f / (1.f + expf(-go));
        float cn = fg * g_c[b * Hd + k] + ig * cg;
        float hn = og * tanhf(cn);
        g_c[b * Hd + k]  = cn;
        g_hT[k * Bq + b] = hn;
        __nv_bfloat16 hi = __float2bfloat16(hn);
        g_hb_hi[b * Hd + k] = hi;
        g_hb_lo[b * Hd + k] = __float2bfloat16(hn - __bfloat162float(hi));
    }
}

// ---------------- logits via mma.sync bf16 3-term split + argmax + decide ---
// 250 blocks x 256 threads (8 warps, 4 m x 2 n, 32x32 warp tiles).
// Mainloop identical to the verified R15 kernel; decide fused via last-block.
#define KC 64
#define NCH 16
#define AROW 144
#define SM_A_HI 0
#define SM_A_LO 18432            // 128*144
#define SM_B_HI 36864
#define SM_B_LO 46080            // + 64*144
#define STAGE   55296
#define SMEM_SZ (2 * STAGE)      // 110592

__device__ __forceinline__ void stage_chunk(uint32_t sbs, int c, int v0, int tid) {
#pragma unroll
    for (int j = 0; j < 12; j++) {
        int idx = tid + j * 256;
        const __nv_bfloat16* g;
        uint32_t sa;
        if (idx < 2048) {
            int var = idx >> 10;
            int rem = idx & 1023;
            int row = rem >> 3, ch = rem & 7;
            const __nv_bfloat16* base = var ? g_wt_lo : g_wt_hi;
            g = base + (size_t)(v0 + row) * Hd + c * KC + ch * 8;
            sa = sbs + (var ? SM_A_LO : SM_A_HI) + row * AROW + ch * 16;
        } else {
            int rem = idx - 2048;
            int var = rem >> 9;
            int r2 = rem & 511;
            int row = r2 >> 3, ch = r2 & 7;
            const __nv_bfloat16* base = var ? g_hb_lo : g_hb_hi;
            g = base + (size_t)row * Hd + c * KC + ch * 8;
            sa = sbs + (var ? SM_B_LO : SM_B_HI) + row * AROW + ch * 16;
        }
        CP_ASYNC16(sa, g);
    }
}

__global__ __launch_bounds__(256, 2) void k_logits_mma(const float* __restrict__ out_b,
                                                       const float* __restrict__ std_t,
                                                       float* __restrict__ out_tok,
                                                       int write_tok) {
    if (*(volatile int*)&g_active == 0) return;
    extern __shared__ __align__(16) char smem[];
    uint32_t sb = smem_u32(smem);
    int tid = threadIdx.x;
    int wid = tid >> 5, lid = tid & 31;
    int wm = wid & 3, wn = wid >> 2;
    int r = lid >> 2, tg = lid & 3;
    int v0 = blockIdx.x * 128;

    float acc[2][4][4];
#pragma unroll
    for (int ti = 0; ti < 2; ti++)
#pragma unroll
        for (int tj = 0; tj < 4; tj++)
#pragma unroll
            for (int q = 0; q < 4; q++) acc[ti][tj][q] = 0.f;

    stage_chunk(sb, 0, v0, tid);
    CP_COMMIT();

    for (int c = 0; c < NCH; c++) {
        if (c + 1 < NCH) {
            stage_chunk(sb + (uint32_t)((c + 1) & 1) * STAGE, c + 1, v0, tid);
            CP_COMMIT();
            CP_WAIT1();
        } else {
            CP_WAIT0();
        }
        __syncthreads();

        const char* base = smem + (size_t)(c & 1) * STAGE;
        const char* pAh = base + SM_A_HI;
        const char* pAl = base + SM_A_LO;
        const char* pBh = base + SM_B_HI;
        const char* pBl = base + SM_B_LO;

#pragma unroll
        for (int ks = 0; ks < KC / 16; ks++) {
            int kb0 = ks * 32 + tg * 4;
            uint32_t Ah[2][4], Al[2][4], Bh[4][2], Bl[4][2];
#pragma unroll
            for (int ti = 0; ti < 2; ti++) {
                int m0 = wm * 32 + ti * 16 + r;
                Ah[ti][0] = *(const uint32_t*)(pAh + m0 * AROW + kb0);
                Ah[ti][1] = *(const uint32_t*)(pAh + (m0 + 8) * AROW + kb0);
                Ah[ti][2] = *(const uint32_t*)(pAh + m0 * AROW + kb0 + 16);
                Ah[ti][3] = *(const uint32_t*)(pAh + (m0 + 8) * AROW + kb0 + 16);
                Al[ti][0] = *(const uint32_t*)(pAl + m0 * AROW + kb0);
                Al[ti][1] = *(const uint32_t*)(pAl + (m0 + 8) * AROW + kb0);
                Al[ti][2] = *(const uint32_t*)(pAl + m0 * AROW + kb0 + 16);
                Al[ti][3] = *(const uint32_t*)(pAl + (m0 + 8) * AROW + kb0 + 16);
            }
#pragma unroll
            for (int tj = 0; tj < 4; tj++) {
                int n0 = wn * 32 + tj * 8 + r;
                Bh[tj][0] = *(const uint32_t*)(pBh + n0 * AROW + kb0);
                Bh[tj][1] = *(const uint32_t*)(pBh + n0 * AROW + kb0 + 16);
                Bl[tj][0] = *(const uint32_t*)(pBl + n0 * AROW + kb0);
                Bl[tj][1] = *(const uint32_t*)(pBl + n0 * AROW + kb0 + 16);
            }
#pragma unroll
            for (int ti = 0; ti < 2; ti++)
#pragma unroll
                for (int tj = 0; tj < 4; tj++) {
                    mma_bf16(acc[ti][tj], Ah[ti][0], Ah[ti][1], Ah[ti][2], Ah[ti][3],
                             Bh[tj][0], Bh[tj][1]);
                    mma_bf16(acc[ti][tj], Ah[ti][0], Ah[ti][1], Ah[ti][2], Ah[ti][3],
                             Bl[tj][0], Bl[tj][1]);
                    mma_bf16(acc[ti][tj], Al[ti][0], Al[ti][1], Al[ti][2], Al[ti][3],
                             Bh[tj][0], Bh[tj][1]);
                }
        }
        __syncthreads();
    }

    // ---- epilogue: stage std/bias coalesced, add, warp-level argmax ----
    float* s_std  = (float*)smem;                 // [64][132] fp32
    float* s_bias = (float*)(smem + 33792);       // [128]
    float* s_rv   = (float*)(smem + 34816);       // [64 cols][4 wm]
    int*   s_ri   = (int*)(smem + 35840);
#pragma unroll
    for (int j = 0; j < 8; j++) {
        int idx = tid + j * 256;
        int row = idx >> 5, c4 = idx & 31;
        float4 v = *(const float4*)(std_t + (size_t)row * Vv + v0 + c4 * 4);
        *(float4*)(s_std + row * 132 + c4 * 4) = v;
    }
    if (tid < 32) ((float4*)s_bias)[tid] = ((const float4*)(out_b + v0))[tid];
    __syncthreads();

#pragma unroll
    for (int tj = 0; tj < 4; tj++) {
#pragma unroll
        for (int p = 0; p < 2; p++) {
            int n = wn * 32 + tj * 8 + tg * 2 + p;
            float best = -1e30f;
            int bi = 0x7fffffff;
#pragma unroll
            for (int ti = 0; ti < 2; ti++)
#pragma unroll
                for (int hh = 0; hh < 2; hh++) {
                    int row = wm * 32 + ti * 16 + r + hh * 8;
                    float val = acc[ti][tj][hh * 2 + p] + s_bias[row] + s_std[n * 132 + row];
                    int idx = v0 + row;
                    if (val > best || (val == best && idx < bi)) { best = val; bi = idx; }
                }
#pragma unroll
            for (int o = 16; o >= 4; o >>= 1) {
                float ov = __shfl_down_sync(0xffffffffu, best, o);
                int oi   = __shfl_down_sync(0xffffffffu, bi, o);
                if (ov > best || (ov == best && oi < bi)) { best = ov; bi = oi; }
            }
            if (lid < 4) {
                s_rv[n * 4 + wm] = best;
                s_ri[n * 4 + wm] = bi;
            }
        }
    }
    __syncthreads();
    if (tid < 64) {
        float best = -1e30f;
        int bi = 0x7fffffff;
#pragma unroll
        for (int j = 0; j < 4; j++) {
            float vv = s_rv[tid * 4 + j];
            int ii = s_ri[tid * 4 + j];
            if (vv > best || (vv == best && ii < bi)) { best = vv; bi = ii; }
        }
        g_pval[blockIdx.x * Bq + tid] = best;
        g_pidx[blockIdx.x * Bq + tid] = bi;
    }

    // ---- fused decide: last block of this step reduces all partials ----
    __shared__ int s_last;
    __syncthreads();
    __threadfence();
    if (tid == 0) {
        int t0 = atomicAdd(&g_ldone, 1);
        s_last = ((t0 % NLBLK) == NLBLK - 1) ? 1 : 0;
    }
    __syncthreads();
    if (!s_last) return;
    __threadfence();

    int*  s_mx = (int*)smem;                      // [64]
    {
        int b = tid >> 2, s = tid & 3;            // 4 threads per batch row
        float best = -1e30f;
        int bi = 0x7fffffff;
        for (int blk = s; blk < NLBLK; blk += 4) {
            float v = __ldcg(&g_pval[blk * Bq + b]);
            int   i = __ldcg(&g_pidx[blk * Bq + b]);
            if (v > best || (v == best && i < bi)) { best = v; bi = i; }
        }
#pragma unroll
        for (int o = 1; o < 4; o <<= 1) {         // butterfly within group of 4
            float ov = __shfl_xor_sync(0xffffffffu, best, o);
            int oi   = __shfl_xor_sync(0xffffffffu, bi, o);
            if (ov > best || (ov == best && oi < bi)) { best = ov; bi = oi; }
        }
        if (s == 0) {
            g_tok[b] = bi;
            if (write_tok) out_tok[b] = (float)bi;
            s_mx[b] = bi;
        }
    }
    __syncthreads();
    if (tid < 32) {
        int m = max(s_mx[tid], s_mx[tid + 32]);
#pragma unroll
        for (int o = 16; o > 0; o >>= 1)
            m = max(m, __shfl_down_sync(0xffffffffu, m, o));
        if (tid == 0 && m <= 0) g_active = 0;
    }
}

// ---------------- write final hidden state ---------------------------------
__global__ void k_final(float* __restrict__ out_h) {
    int b = blockIdx.x;
    for (int k = threadIdx.x; k < Hd; k += blockDim.x)
        out_h[b * Hd + k] = g_hT[k * Bq + b];
}

// ---------------- launcher -------------------------------------------------
extern "C" void kernel_launch(void* const* d_in, const int* in_sizes, int n_in,
                              void* d_out, int out_size) {
    const float* std_in = (const float*)d_in[1];
    const float* h_in   = (const float*)d_in[2];
    const float* c_in   = (const float*)d_in[3];
    const float* emb    = (const float*)d_in[4];
    const float* w_ih   = (const float*)d_in[5];
    const float* w_hh   = (const float*)d_in[6];
    const float* b_ih   = (const float*)d_in[7];
    const float* b_hh   = (const float*)d_in[8];
    const float* out_w  = (const float*)d_in[9];
    const float* out_b  = (const float*)d_in[10];
    float* out = (float*)d_out;

    int write_tok = (out_size >= NSTEP * Bq) ? 1 : 0;
    int write_h   = (out_size == Hd * Bq || out_size >= NSTEP * Bq + Hd * Bq) ? 1 : 0;
    int h_off     = (out_size >= NSTEP * Bq + Hd * Bq) ? NSTEP * Bq : 0;

    cudaFuncSetAttribute(k_logits_mma, cudaFuncAttributeMaxDynamicSharedMemorySize, SMEM_SZ);

    k_init<<<Bq, 256>>>(h_in, c_in);
    k_wsplit<<<dim3(1000, 32), dim3(32, 8)>>>(out_w);
    for (int t = 0; t < NSTEP; t++) {
        k_gateslstm<<<dim3(128, 2), 256>>>(emb, w_ih, w_hh, b_ih, b_hh);
        k_logits_mma<<<NLBLK, 256, SMEM_SZ>>>(out_b, std_in + (size_t)t * Bq * Vv,
                                              out + (size_t)t * Bq, write_tok);
    }
    if (write_h) k_final<<<Bq, 256>>>(out + h_off);
}